// round 16
// baseline (speedup 1.0000x reference)
#include <cuda_runtime.h>
#include <cfloat>

// N=8192 tokens, K=4096, D=1024.
//   idx[n] = argmax_k x[n,k]  (first-occurrence tie-break)
//   out[n,d] = W[d, idx[n]]
//
// K1: smem transpose W [D,K] -> g_Wt [K,D], 1024 blocks + PDL trigger.
//     v2 staging: STS.128 stores the tile untransposed (7 mem-instr per 16B
//     vs 10 in the old 4xSTS.32 scheme); the 4-way scatter moves to the
//     LDS.32 read side. Row stride padded to 68 floats (16B-aligned, ~2-way
//     conflicts only).
// K2: R7's proven fused argmax + row gather, 8192 blocks x 1 token (PDL
//     consumer, cudaGridDependencySynchronize before touching g_Wt).

#define NTOK 8192
#define KDIM 4096
#define DDIM 1024
#define TP_TILE 64
#define TP_BLOCKS ((KDIM / TP_TILE) * (DDIM / TP_TILE))   // 1024

__device__ float g_Wt[(size_t)KDIM * DDIM];   // 16 MB scratch

// ---------------- K1: transpose, STS.128 staging ----------------
__global__ void __launch_bounds__(256) transpose_kernel(const float* __restrict__ W)
{
#if __CUDA_ARCH__ >= 900
    cudaTriggerProgrammaticLaunchCompletion();   // let K2 co-schedule
#endif
    __shared__ float st[TP_TILE][68];            // 68 floats: 272B rows, 16B-aligned
    const int bid = blockIdx.x;
    const int tid = threadIdx.x;
    const int k0 = (bid % (KDIM / TP_TILE)) * TP_TILE;
    const int d0 = (bid / (KDIM / TP_TILE)) * TP_TILE;
    const int c  = tid & 15;     // float4 lane within a 64-float row
    const int r0 = tid >> 4;     // 0..15

    // load: W rows (d-major) -> smem untransposed, one STS.128 per float4
    #pragma unroll
    for (int p = 0; p < 4; ++p) {
        int r = r0 + 16 * p;     // d offset within tile
        float4 v = __ldcs(reinterpret_cast<const float4*>(
            W + (size_t)(d0 + r) * KDIM + (k0 + 4 * c)));
        *reinterpret_cast<float4*>(&st[r][4 * c]) = v;
    }
    __syncthreads();

    // store: gather a Wt-row float4 (4 consecutive d, same k) via 4 LDS.32,
    // then one coalesced STG.128 into g_Wt
    #pragma unroll
    for (int p = 0; p < 4; ++p) {
        int k = r0 + 16 * p;     // k offset within tile
        float4 o;
        o.x = st[4 * c + 0][k];
        o.y = st[4 * c + 1][k];
        o.z = st[4 * c + 2][k];
        o.w = st[4 * c + 3][k];
        *reinterpret_cast<float4*>(
            g_Wt + (size_t)(k0 + k) * DDIM + (d0 + 4 * c)) = o;
    }
}

// ---------------- K2: fused argmax + row gather (R7 verbatim) ----------------
__global__ void __launch_bounds__(256) argmax_gather_kernel(
    const float* __restrict__ x, float* __restrict__ out)
{
    const int n   = blockIdx.x;
    const int tid = threadIdx.x;

    // ---- argmax phase: only reads x, overlaps K1 ----
    const float4* xr = reinterpret_cast<const float4*>(x + (size_t)n * KDIM);
    float best = -FLT_MAX;
    int   bi   = 0x7fffffff;

    #pragma unroll
    for (int it = 0; it < (KDIM / 4) / 256; ++it) {
        int c = tid + it * 256;
        float4 v = __ldcs(xr + c);
        int base = c * 4;
        if (v.x > best) { best = v.x; bi = base + 0; }
        if (v.y > best) { best = v.y; bi = base + 1; }
        if (v.z > best) { best = v.z; bi = base + 2; }
        if (v.w > best) { best = v.w; bi = base + 3; }
    }

    // warp reduce (smaller index wins ties)
    #pragma unroll
    for (int off = 16; off > 0; off >>= 1) {
        float ov = __shfl_down_sync(0xffffffffu, best, off);
        int   oi = __shfl_down_sync(0xffffffffu, bi,   off);
        if (ov > best || (ov == best && oi < bi)) { best = ov; bi = oi; }
    }

    // block reduce across 8 warps
    __shared__ float s_val[8];
    __shared__ int   s_idx[8];
    __shared__ int   s_final;
    int warp = tid >> 5;
    int lane = tid & 31;
    if (lane == 0) { s_val[warp] = best; s_idx[warp] = bi; }
    __syncthreads();
    if (warp == 0) {
        best = (lane < 8) ? s_val[lane] : -FLT_MAX;
        bi   = (lane < 8) ? s_idx[lane] : 0x7fffffff;
        #pragma unroll
        for (int off = 4; off > 0; off >>= 1) {
            float ov = __shfl_down_sync(0xffffffffu, best, off);
            int   oi = __shfl_down_sync(0xffffffffu, bi,   off);
            if (ov > best || (ov == best && oi < bi)) { best = ov; bi = oi; }
        }
        if (lane == 0) s_final = bi;
    }
    __syncthreads();
    const int idx = s_final;

    // ---- wait for K1 (transpose) completion + memory flush ----
#if __CUDA_ARCH__ >= 900
    cudaGridDependencySynchronize();
#endif

    // ---- coalesced row copy: out[n,:] = g_Wt[idx,:] ----
    const float4* src = reinterpret_cast<const float4*>(g_Wt + (size_t)idx * DDIM);
    float4*       dst = reinterpret_cast<float4*>(out + (size_t)n * DDIM);
    __stcs(dst + tid, src[tid]);
}

extern "C" void kernel_launch(void* const* d_in, const int* in_sizes, int n_in,
                              void* d_out, int out_size) {
    const float* x = (const float*)d_in[0];   // [N, K]
    const float* W = (const float*)d_in[1];   // [D, K]
    float* out = (float*)d_out;               // [N, D]

    transpose_kernel<<<TP_BLOCKS, 256>>>(W);

    cudaLaunchConfig_t cfg = {};
    cfg.gridDim  = dim3(NTOK, 1, 1);
    cfg.blockDim = dim3(256, 1, 1);
    cfg.dynamicSmemBytes = 0;
    cfg.stream = 0;
    cudaLaunchAttribute attr[1];
    attr[0].id = cudaLaunchAttributeProgrammaticStreamSerialization;
    attr[0].val.programmaticStreamSerializationAllowed = 1;
    cfg.attrs = attr;
    cfg.numAttrs = 1;
    cudaLaunchKernelEx(&cfg, argmax_gather_kernel, x, out);
}

// round 17
// speedup vs baseline: 1.1302x; 1.1302x over previous
#include <cuda_runtime.h>
#include <cfloat>

// N=8192 tokens, K=4096, D=1024.
//   idx[n] = argmax_k x[n,k]  (first-occurrence tie-break)
//   out[n,d] = W[d, idx[n]]
//
// FINAL (R7 config — measured 33.5 us, ~1 us above the 192 MB @ 5.9 TB/s
// pipelined floor):
// K1: float4 smem transpose W [D,K] -> g_Wt [K,D], 1024 blocks, PDL trigger.
//     Its exposed span (~5.3 us) equals its own 32 MB DRAM time — i.e. the
//     pipeline with K2 is already perfect.
// K2: fused per-token argmax + row gather (PDL consumer). Argmax streams x
//     with __ldcs (evict-first; protects the 16 MB Wt L2 working set),
//     cudaGridDependencySynchronize() gates the gather on K1 completion,
//     out written with __stcs. 8192 blocks x 1 token: only ~2% of blocks
//     ever park at the PDL barrier (every batched variant measured worse).

#define NTOK 8192
#define KDIM 4096
#define DDIM 1024
#define TP_TILE 64
#define TP_BLOCKS ((KDIM / TP_TILE) * (DDIM / TP_TILE))   // 1024

__device__ float g_Wt[(size_t)KDIM * DDIM];   // 16 MB scratch

// ---------------- K1: transpose, float4 both sides ----------------
__global__ void __launch_bounds__(256) transpose_kernel(const float* __restrict__ W)
{
#if __CUDA_ARCH__ >= 900
    cudaTriggerProgrammaticLaunchCompletion();   // let K2 co-schedule
#endif
    __shared__ float t[TP_TILE][TP_TILE + 1];
    const int bid = blockIdx.x;
    const int tid = threadIdx.x;
    const int k0 = (bid % (KDIM / TP_TILE)) * TP_TILE;
    const int d0 = (bid / (KDIM / TP_TILE)) * TP_TILE;
    const int tx = tid & 15;     // float4 lane along fast dim
    const int ty = tid >> 4;     // row 0..15

    #pragma unroll
    for (int i = 0; i < 4; ++i) {
        int r = ty + 16 * i;
        float4 v = __ldcs(reinterpret_cast<const float4*>(
            W + (size_t)(d0 + r) * KDIM + (k0 + 4 * tx)));
        t[r][4 * tx + 0] = v.x;
        t[r][4 * tx + 1] = v.y;
        t[r][4 * tx + 2] = v.z;
        t[r][4 * tx + 3] = v.w;
    }
    __syncthreads();

    #pragma unroll
    for (int i = 0; i < 4; ++i) {
        int r = ty + 16 * i;
        float4 v;
        v.x = t[4 * tx + 0][r];
        v.y = t[4 * tx + 1][r];
        v.z = t[4 * tx + 2][r];
        v.w = t[4 * tx + 3][r];
        *reinterpret_cast<float4*>(
            g_Wt + (size_t)(k0 + r) * DDIM + (d0 + 4 * tx)) = v;
    }
}

// ---------------- K2: fused argmax + row gather (PDL consumer) ----------------
__global__ void __launch_bounds__(256) argmax_gather_kernel(
    const float* __restrict__ x, float* __restrict__ out)
{
    const int n   = blockIdx.x;
    const int tid = threadIdx.x;

    // ---- argmax phase: only reads x, overlaps K1 ----
    const float4* xr = reinterpret_cast<const float4*>(x + (size_t)n * KDIM);
    float best = -FLT_MAX;
    int   bi   = 0x7fffffff;

    #pragma unroll
    for (int it = 0; it < (KDIM / 4) / 256; ++it) {
        int c = tid + it * 256;
        float4 v = __ldcs(xr + c);
        int base = c * 4;
        if (v.x > best) { best = v.x; bi = base + 0; }
        if (v.y > best) { best = v.y; bi = base + 1; }
        if (v.z > best) { best = v.z; bi = base + 2; }
        if (v.w > best) { best = v.w; bi = base + 3; }
    }

    // warp reduce (smaller index wins ties)
    #pragma unroll
    for (int off = 16; off > 0; off >>= 1) {
        float ov = __shfl_down_sync(0xffffffffu, best, off);
        int   oi = __shfl_down_sync(0xffffffffu, bi,   off);
        if (ov > best || (ov == best && oi < bi)) { best = ov; bi = oi; }
    }

    // block reduce across 8 warps
    __shared__ float s_val[8];
    __shared__ int   s_idx[8];
    __shared__ int   s_final;
    int warp = tid >> 5;
    int lane = tid & 31;
    if (lane == 0) { s_val[warp] = best; s_idx[warp] = bi; }
    __syncthreads();
    if (warp == 0) {
        best = (lane < 8) ? s_val[lane] : -FLT_MAX;
        bi   = (lane < 8) ? s_idx[lane] : 0x7fffffff;
        #pragma unroll
        for (int off = 4; off > 0; off >>= 1) {
            float ov = __shfl_down_sync(0xffffffffu, best, off);
            int   oi = __shfl_down_sync(0xffffffffu, bi,   off);
            if (ov > best || (ov == best && oi < bi)) { best = ov; bi = oi; }
        }
        if (lane == 0) s_final = bi;
    }
    __syncthreads();
    const int idx = s_final;

    // ---- wait for K1 (transpose) completion + memory flush ----
#if __CUDA_ARCH__ >= 900
    cudaGridDependencySynchronize();
#endif

    // ---- coalesced row copy: out[n,:] = g_Wt[idx,:] (Wt reads hit L2) ----
    const float4* src = reinterpret_cast<const float4*>(g_Wt + (size_t)idx * DDIM);
    float4*       dst = reinterpret_cast<float4*>(out + (size_t)n * DDIM);
    __stcs(dst + tid, src[tid]);
}

extern "C" void kernel_launch(void* const* d_in, const int* in_sizes, int n_in,
                              void* d_out, int out_size) {
    const float* x = (const float*)d_in[0];   // [N, K]
    const float* W = (const float*)d_in[1];   // [D, K]
    float* out = (float*)d_out;               // [N, D]

    transpose_kernel<<<TP_BLOCKS, 256>>>(W);

    // K2 with programmatic dependent launch: may start while K1 runs;
    // in-kernel cudaGridDependencySynchronize() provides the data dependency.
    cudaLaunchConfig_t cfg = {};
    cfg.gridDim  = dim3(NTOK, 1, 1);
    cfg.blockDim = dim3(256, 1, 1);
    cfg.dynamicSmemBytes = 0;
    cfg.stream = 0;
    cudaLaunchAttribute attr[1];
    attr[0].id = cudaLaunchAttributeProgrammaticStreamSerialization;
    attr[0].val.programmaticStreamSerializationAllowed = 1;
    cfg.attrs = attr;
    cfg.numAttrs = 1;
    cudaLaunchKernelEx(&cfg, argmax_gather_kernel, x, out);
}